// round 2
// baseline (speedup 1.0000x reference)
#include <cuda_runtime.h>
#include <cstdint>

#define NUM_CLASSES 17929
#define BATCH       512
#define NUM_MODELS  16
#define HIDDEN      4
#define BCHUNK      128           // batch rows per block (grid.y = 512/128 = 4)
#define TPB         256

__global__ void __launch_bounds__(TPB)
family_mlp_kernel(const float* __restrict__ x,     // [M, B, C]
                  const float* __restrict__ W1,    // [C, H, M]
                  const float* __restrict__ b1,    // [C, H]
                  const float* __restrict__ W2,    // [C, H]
                  const float* __restrict__ b2,    // [C]
                  float* __restrict__ out)         // [B, C]
{
    const int c = blockIdx.x * TPB + threadIdx.x;
    if (c >= NUM_CLASSES) return;

    // ---- load per-class parameters into registers (amortized over BCHUNK) ----
    float w1[HIDDEN][NUM_MODELS];
    {
        const float4* W1v = reinterpret_cast<const float4*>(W1 + (size_t)c * (HIDDEN * NUM_MODELS));
        #pragma unroll
        for (int i = 0; i < (HIDDEN * NUM_MODELS) / 4; ++i) {
            float4 v = __ldg(&W1v[i]);
            int h = (i * 4) / NUM_MODELS;
            int m = (i * 4) % NUM_MODELS;
            w1[h][m + 0] = v.x;
            w1[h][m + 1] = v.y;
            w1[h][m + 2] = v.z;
            w1[h][m + 3] = v.w;
        }
    }
    float4 bias1 = __ldg(reinterpret_cast<const float4*>(b1) + c);
    float4 w2    = __ldg(reinterpret_cast<const float4*>(W2) + c);
    float  bias2 = __ldg(b2 + c);

    const int b0 = blockIdx.y * BCHUNK;
    const size_t plane = (size_t)BATCH * NUM_CLASSES;   // stride between model slices

    const float* xbase = x + (size_t)b0 * NUM_CLASSES + c;
    float* obase       = out + (size_t)b0 * NUM_CLASSES + c;

    for (int bi = 0; bi < BCHUNK; ++bi) {
        const float* xp = xbase + (size_t)bi * NUM_CLASSES;

        float h0 = bias1.x, h1 = bias1.y, h2 = bias1.z, h3 = bias1.w;

        #pragma unroll
        for (int m = 0; m < NUM_MODELS; ++m) {
            // streaming load: x has zero reuse; keep L2 for the weights
            float xv = __ldcs(xp + (size_t)m * plane);
            h0 = fmaf(xv, w1[0][m], h0);
            h1 = fmaf(xv, w1[1][m], h1);
            h2 = fmaf(xv, w1[2][m], h2);
            h3 = fmaf(xv, w1[3][m], h3);
        }

        float acc = bias2;
        acc = fmaf(fmaxf(h0, 0.0f), w2.x, acc);
        acc = fmaf(fmaxf(h1, 0.0f), w2.y, acc);
        acc = fmaf(fmaxf(h2, 0.0f), w2.z, acc);
        acc = fmaf(fmaxf(h3, 0.0f), w2.w, acc);

        __stcs(obase + (size_t)bi * NUM_CLASSES, acc);
    }
}

extern "C" void kernel_launch(void* const* d_in, const int* in_sizes, int n_in,
                              void* d_out, int out_size)
{
    const float* x  = (const float*)d_in[0];   // [16, 512, 17929]
    const float* W1 = (const float*)d_in[1];   // [17929, 4, 16]
    const float* b1 = (const float*)d_in[2];   // [17929, 4]
    const float* W2 = (const float*)d_in[3];   // [17929, 4]
    const float* b2 = (const float*)d_in[4];   // [17929]
    float* out = (float*)d_out;                // [512, 17929]

    dim3 grid((NUM_CLASSES + TPB - 1) / TPB, BATCH / BCHUNK);
    family_mlp_kernel<<<grid, TPB>>>(x, W1, b1, W2, b2, out);
}

// round 3
// speedup vs baseline: 1.0195x; 1.0195x over previous
#include <cuda_runtime.h>
#include <cstdint>

#define NUM_CLASSES 17929
#define BATCH       512
#define NUM_MODELS  16
#define HIDDEN      4
#define TPB         256
#define CPB         (TPB / 2)     // 128 classes per block (2 threads per class)
#define BCHUNK      128           // batch rows per block (grid.y = 4)

__global__ void __launch_bounds__(TPB)
family_mlp_kernel(const float* __restrict__ x,     // [M, B, C]
                  const float* __restrict__ W1,    // [C, H, M]
                  const float* __restrict__ b1,    // [C, H]
                  const float* __restrict__ W2,    // [C, H]
                  const float* __restrict__ b2,    // [C]
                  float* __restrict__ out)         // [B, C]
{
    const int tid  = threadIdx.x;
    const int half = tid & 1;            // which 8 models this thread owns
    int c = blockIdx.x * CPB + (tid >> 1);
    const bool valid = (c < NUM_CLASSES);
    if (!valid) c = NUM_CLASSES - 1;     // clamp: keep shuffles well-defined

    // ---- per-class weights for this thread's 8 models (32 regs) ----
    float w1[HIDDEN][8];
    {
        const float* Wb = W1 + (size_t)c * (HIDDEN * NUM_MODELS) + half * 8;
        #pragma unroll
        for (int h = 0; h < HIDDEN; ++h) {
            float4 a = __ldg(reinterpret_cast<const float4*>(Wb + h * NUM_MODELS));
            float4 b = __ldg(reinterpret_cast<const float4*>(Wb + h * NUM_MODELS + 4));
            w1[h][0] = a.x; w1[h][1] = a.y; w1[h][2] = a.z; w1[h][3] = a.w;
            w1[h][4] = b.x; w1[h][5] = b.y; w1[h][6] = b.z; w1[h][7] = b.w;
        }
    }
    const float4 bias1 = __ldg(reinterpret_cast<const float4*>(b1) + c);
    const float4 w2    = __ldg(reinterpret_cast<const float4*>(W2) + c);
    const float  bias2 = __ldg(b2 + c);

    // half 0 seeds the bias so the pairwise sum counts it exactly once
    const float h0i = half ? 0.0f : bias1.x;
    const float h1i = half ? 0.0f : bias1.y;
    const float h2i = half ? 0.0f : bias1.z;
    const float h3i = half ? 0.0f : bias1.w;

    const int b0 = blockIdx.y * BCHUNK;
    const size_t plane = (size_t)BATCH * NUM_CLASSES;

    // base pointer: this thread's first model plane, row b0, class c
    const float* xp = x + (size_t)(half * 8) * plane + (size_t)b0 * NUM_CLASSES + c;
    float* op       = out + (size_t)b0 * NUM_CLASSES + c;

    // ---- software-pipelined main loop over batch rows ----
    float cur[8];
    #pragma unroll
    for (int m = 0; m < 8; ++m)
        cur[m] = __ldcs(xp + m * plane);

    for (int bi = 0; bi < BCHUNK; ++bi) {
        // prefetch next row's 8 values while we compute this row
        float nxt[8];
        if (bi + 1 < BCHUNK) {
            const float* xn = xp + (size_t)(bi + 1) * NUM_CLASSES;
            #pragma unroll
            for (int m = 0; m < 8; ++m)
                nxt[m] = __ldcs(xn + m * plane);
        }

        float h0 = h0i, h1 = h1i, h2 = h2i, h3 = h3i;
        #pragma unroll
        for (int m = 0; m < 8; ++m) {
            h0 = fmaf(cur[m], w1[0][m], h0);
            h1 = fmaf(cur[m], w1[1][m], h1);
            h2 = fmaf(cur[m], w1[2][m], h2);
            h3 = fmaf(cur[m], w1[3][m], h3);
        }

        // combine the two model-halves (partner lane is tid^1)
        h0 += __shfl_xor_sync(0xFFFFFFFFu, h0, 1);
        h1 += __shfl_xor_sync(0xFFFFFFFFu, h1, 1);
        h2 += __shfl_xor_sync(0xFFFFFFFFu, h2, 1);
        h3 += __shfl_xor_sync(0xFFFFFFFFu, h3, 1);

        float acc = bias2;
        acc = fmaf(fmaxf(h0, 0.0f), w2.x, acc);
        acc = fmaf(fmaxf(h1, 0.0f), w2.y, acc);
        acc = fmaf(fmaxf(h2, 0.0f), w2.z, acc);
        acc = fmaf(fmaxf(h3, 0.0f), w2.w, acc);

        if (half == 0 && valid)
            __stcs(op + (size_t)bi * NUM_CLASSES, acc);

        #pragma unroll
        for (int m = 0; m < 8; ++m)
            cur[m] = nxt[m];
    }
}

extern "C" void kernel_launch(void* const* d_in, const int* in_sizes, int n_in,
                              void* d_out, int out_size)
{
    const float* x  = (const float*)d_in[0];   // [16, 512, 17929]
    const float* W1 = (const float*)d_in[1];   // [17929, 4, 16]
    const float* b1 = (const float*)d_in[2];   // [17929, 4]
    const float* W2 = (const float*)d_in[3];   // [17929, 4]
    const float* b2 = (const float*)d_in[4];   // [17929]
    float* out = (float*)d_out;                // [512, 17929]

    dim3 grid((NUM_CLASSES + CPB - 1) / CPB, BATCH / BCHUNK);
    family_mlp_kernel<<<grid, TPB>>>(x, W1, b1, W2, b2, out);
}

// round 5
// speedup vs baseline: 1.4016x; 1.3748x over previous
#include <cuda_runtime.h>
#include <cstdint>

#define NUM_CLASSES 17929
#define BATCH       512
#define NUM_MODELS  16
#define HIDDEN      4

#define TILE_C      512            // classes per CTA (== TPB)
#define TPB         512
#define BT          2              // batch rows per tile
#define RPC         128            // batch rows per CTA  (grid.y = 4)
#define NT          (RPC / BT)     // 64 tiles per CTA
#define STAGES      3
#define TILE_FLOATS (NUM_MODELS * BT * TILE_C)   // 16384
#define TILE_BYTES  (TILE_FLOATS * 4)            // 65536
#define SMEM_BYTES  (STAGES * TILE_BYTES)        // 196608

__device__ __forceinline__ void cp_async4(uint32_t dst, const float* src) {
    asm volatile("cp.async.ca.shared.global [%0], [%1], 4;\n" :: "r"(dst), "l"(src));
}
__device__ __forceinline__ void cp_commit() {
    asm volatile("cp.async.commit_group;\n" ::: "memory");
}
__device__ __forceinline__ void cp_wait1() {
    asm volatile("cp.async.wait_group 1;\n" ::: "memory");
}
__device__ __forceinline__ void cp_wait0() {
    asm volatile("cp.async.wait_group 0;\n" ::: "memory");
}

extern __shared__ float smem[];    // [STAGES][16*BT][TILE_C]

__global__ void __launch_bounds__(TPB, 1)
family_mlp_kernel(const float* __restrict__ x,     // [M, B, C]
                  const float* __restrict__ W1,    // [C, H, M]
                  const float* __restrict__ b1,    // [C, H]
                  const float* __restrict__ W2,    // [C, H]
                  const float* __restrict__ b2,    // [C]
                  float* __restrict__ out)         // [B, C]
{
    const int tid = threadIdx.x;
    int c0 = blockIdx.x * TILE_C;
    if (c0 > NUM_CLASSES - TILE_C) c0 = NUM_CLASSES - TILE_C;   // overlap last block
    const int c  = c0 + tid;
    const int r0 = blockIdx.y * RPC;

    // ---- per-class weights in registers (64 + 9 floats) ----
    float w1[HIDDEN][NUM_MODELS];
    {
        const float4* wv = reinterpret_cast<const float4*>(W1) + (size_t)c * 16;
        #pragma unroll
        for (int k = 0; k < 16; ++k) {
            float4 v = __ldg(wv + k);
            const int h = k >> 2, mm = (k & 3) * 4;
            w1[h][mm + 0] = v.x; w1[h][mm + 1] = v.y;
            w1[h][mm + 2] = v.z; w1[h][mm + 3] = v.w;
        }
    }
    const float4 bb1 = __ldg(reinterpret_cast<const float4*>(b1) + c);
    const float4 ww2 = __ldg(reinterpret_cast<const float4*>(W2) + c);
    const float  bb2 = __ldg(b2 + c);

    const size_t plane = (size_t)BATCH * NUM_CLASSES;
    const float* pbase = x   + (size_t)r0 * NUM_CLASSES + c;   // m=0, row r0, class c
    float*       obase = out + (size_t)r0 * NUM_CLASSES + c;

    uint32_t sbase;
    asm("{ .reg .u64 t; cvta.to.shared.u64 t, %1; cvt.u32.u64 %0, t; }"
        : "=r"(sbase) : "l"(smem));
    sbase += tid * 4;   // this thread's column

    // issue one tile's 32 copies (16 models x BT rows, this thread's class only)
    auto issue_tile = [&](int t) {
        const int stage = t % STAGES;
        const uint32_t d0 = sbase + stage * TILE_BYTES;
        const float* p = pbase + (size_t)(t * BT) * NUM_CLASSES;
        #pragma unroll
        for (int q = 0; q < NUM_MODELS * BT; ++q) {           // q = m*BT + b
            const float* src = p + (size_t)(q >> 1) * plane + (size_t)(q & 1) * NUM_CLASSES;
            cp_async4(d0 + q * (TILE_C * 4), src);
        }
        cp_commit();
    };

    // ---- prologue: fill STAGES-1 stages ----
    issue_tile(0);
    issue_tile(1);

    #pragma unroll 1
    for (int t = 0; t < NT; ++t) {
        // committed-so-far = min(t+2, NT); tile t must be complete:
        //   t < NT-1  -> exactly 1 younger group may stay pending
        //   t == NT-1 -> nothing younger exists; drain fully
        if (t == NT - 1) cp_wait0(); else cp_wait1();
        if (t + STAGES - 1 < NT) issue_tile(t + STAGES - 1);

        const int stage = t % STAGES;
        const float* buf = smem + stage * TILE_FLOATS + tid;

        #pragma unroll
        for (int b = 0; b < BT; ++b) {
            float h0 = bb1.x, h1 = bb1.y, h2 = bb1.z, h3 = bb1.w;
            #pragma unroll
            for (int m = 0; m < NUM_MODELS; ++m) {
                const float v = buf[(m * BT + b) * TILE_C];
                h0 = fmaf(v, w1[0][m], h0);
                h1 = fmaf(v, w1[1][m], h1);
                h2 = fmaf(v, w1[2][m], h2);
                h3 = fmaf(v, w1[3][m], h3);
            }
            float acc = bb2;
            acc = fmaf(fmaxf(h0, 0.0f), ww2.x, acc);
            acc = fmaf(fmaxf(h1, 0.0f), ww2.y, acc);
            acc = fmaf(fmaxf(h2, 0.0f), ww2.z, acc);
            acc = fmaf(fmaxf(h3, 0.0f), ww2.w, acc);
            __stcs(obase + (size_t)(t * BT + b) * NUM_CLASSES, acc);
        }
    }
}

extern "C" void kernel_launch(void* const* d_in, const int* in_sizes, int n_in,
                              void* d_out, int out_size)
{
    const float* x  = (const float*)d_in[0];   // [16, 512, 17929]
    const float* W1 = (const float*)d_in[1];   // [17929, 4, 16]
    const float* b1 = (const float*)d_in[2];   // [17929, 4]
    const float* W2 = (const float*)d_in[3];   // [17929, 4]
    const float* b2 = (const float*)d_in[4];   // [17929]
    float* out = (float*)d_out;                // [512, 17929]

    cudaFuncSetAttribute(family_mlp_kernel,
                         cudaFuncAttributeMaxDynamicSharedMemorySize, SMEM_BYTES);

    dim3 grid((NUM_CLASSES + TILE_C - 1) / TILE_C, BATCH / RPC);   // 36 x 4 = 144 CTAs
    family_mlp_kernel<<<grid, TPB, SMEM_BYTES>>>(x, W1, b1, W2, b2, out);
}

// round 6
// speedup vs baseline: 1.7548x; 1.2520x over previous
#include <cuda_runtime.h>
#include <cstdint>

#define NUM_CLASSES 17929
#define BATCH       512
#define NUM_MODELS  16
#define HIDDEN      4

#define TILE_C      512            // classes per CTA (== TPB)
#define TPB         512
#define BT          2              // batch rows per tile
#define RPC         128            // batch rows per CTA  (grid.y = 4)
#define NT          (RPC / BT)     // 64 tiles per CTA
#define STAGES      3
#define PLANES      (NUM_MODELS * BT)            // 32
#define PADW        520                          // 512 + shift(<=3) + pad
#define STAGE_FLOATS (PLANES * PADW)             // 16640
#define STAGE_BYTES  (STAGE_FLOATS * 4)          // 66560
#define SMEM_BYTES   (STAGES * STAGE_BYTES)      // 199680

__device__ __forceinline__ void cp_async16(uint32_t dst, const float* src) {
    asm volatile("cp.async.cg.shared.global [%0], [%1], 16;\n" :: "r"(dst), "l"(src));
}
__device__ __forceinline__ void cp_async4(uint32_t dst, const float* src) {
    asm volatile("cp.async.ca.shared.global [%0], [%1], 4;\n" :: "r"(dst), "l"(src));
}
__device__ __forceinline__ void cp_commit() {
    asm volatile("cp.async.commit_group;\n" ::: "memory");
}
__device__ __forceinline__ void cp_wait1() {
    asm volatile("cp.async.wait_group 1;\n" ::: "memory");
}
__device__ __forceinline__ void cp_wait0() {
    asm volatile("cp.async.wait_group 0;\n" ::: "memory");
}

extern __shared__ float smem[];    // [STAGES][PLANES][PADW]

__global__ void __launch_bounds__(TPB, 1)
family_mlp_kernel(const float* __restrict__ x,     // [M, B, C]
                  const float* __restrict__ W1,    // [C, H, M]
                  const float* __restrict__ b1,    // [C, H]
                  const float* __restrict__ W2,    // [C, H]
                  const float* __restrict__ b2,    // [C]
                  float* __restrict__ out)         // [B, C]
{
    const int tid = threadIdx.x;
    int c0 = blockIdx.x * TILE_C;
    if (c0 > NUM_CLASSES - TILE_C) c0 = NUM_CLASSES - TILE_C;   // overlap last block
    const int c04 = c0 & 3;
    const int c   = c0 + tid;
    const int r0  = blockIdx.y * RPC;

    // ---- per-class weights in registers ----
    float w1[HIDDEN][NUM_MODELS];
    {
        const float4* wv = reinterpret_cast<const float4*>(W1) + (size_t)c * 16;
        #pragma unroll
        for (int k = 0; k < 16; ++k) {
            float4 v = __ldg(wv + k);
            const int h = k >> 2, mm = (k & 3) * 4;
            w1[h][mm + 0] = v.x; w1[h][mm + 1] = v.y;
            w1[h][mm + 2] = v.z; w1[h][mm + 3] = v.w;
        }
    }
    const float4 bb1 = __ldg(reinterpret_cast<const float4*>(b1) + c);
    const float4 ww2 = __ldg(reinterpret_cast<const float4*>(W2) + c);
    const float  bb2 = __ldg(b2 + c);

    const size_t plane = (size_t)BATCH * NUM_CLASSES;
    float* obase = out + (size_t)r0 * NUM_CLASSES + c;

    uint32_t sbase;
    asm("{ .reg .u64 t; cvta.to.shared.u64 t, %1; cvt.u32.u64 %0, t; }"
        : "=r"(sbase) : "l"(smem));

    const int lane = tid & 127;     // position within a plane's 128 copiers
    const int grp  = tid >> 7;      // 0..3: which plane group

    // issue one tile's copies: 32 planes x 128 float4 (+ <=3 tail scalars/plane)
    auto issue_tile = [&](int t) {
        const int stage = t % STAGES;
        const uint32_t s0 = sbase + stage * STAGE_BYTES;
        #pragma unroll
        for (int it = 0; it < PLANES / 4; ++it) {
            const int q = grp + (it << 2);          // 0..31
            const int m = q >> 1, b = q & 1;
            const int a = (c04 + 2 * t + b) & 3;    // misalignment in elements
            const float* g = x + (size_t)m * plane
                               + (size_t)(r0 + 2 * t + b) * NUM_CLASSES + c0;
            const uint32_t dplane = s0 + q * (PADW * 4);
            cp_async16(dplane + lane * 16, (g - a) + lane * 4);
            if (lane < a)   // tail classes c0+512-a .. c0+511 -> slots 512..512+a-1
                cp_async4(dplane + (512 + lane) * 4, g + 512 - a + lane);
        }
        cp_commit();
    };

    // ---- prologue ----
    issue_tile(0);
    issue_tile(1);

    #pragma unroll 1
    for (int t = 0; t < NT; ++t) {
        if (t == NT - 1) cp_wait0(); else cp_wait1();
        __syncthreads();                       // copies are cooperative now
        if (t + STAGES - 1 < NT) issue_tile(t + STAGES - 1);

        const int stage = t % STAGES;
        const float* sb = smem + stage * STAGE_FLOATS;

        #pragma unroll
        for (int b = 0; b < BT; ++b) {
            const int a = (c04 + 2 * t + b) & 3;
            const float* buf = sb + b * PADW + tid + a;   // plane stride 2*PADW over m

            float h0 = bb1.x, h1 = bb1.y, h2 = bb1.z, h3 = bb1.w;
            #pragma unroll
            for (int m = 0; m < NUM_MODELS; ++m) {
                const float v = buf[m * (2 * PADW)];
                h0 = fmaf(v, w1[0][m], h0);
                h1 = fmaf(v, w1[1][m], h1);
                h2 = fmaf(v, w1[2][m], h2);
                h3 = fmaf(v, w1[3][m], h3);
            }
            float acc = bb2;
            acc = fmaf(fmaxf(h0, 0.0f), ww2.x, acc);
            acc = fmaf(fmaxf(h1, 0.0f), ww2.y, acc);
            acc = fmaf(fmaxf(h2, 0.0f), ww2.z, acc);
            acc = fmaf(fmaxf(h3, 0.0f), ww2.w, acc);
            __stcs(obase + (size_t)(2 * t + b) * NUM_CLASSES, acc);
        }
        __syncthreads();   // don't let fast warps overwrite stage t before slow ones read it
    }
}

extern "C" void kernel_launch(void* const* d_in, const int* in_sizes, int n_in,
                              void* d_out, int out_size)
{
    const float* x  = (const float*)d_in[0];   // [16, 512, 17929]
    const float* W1 = (const float*)d_in[1];   // [17929, 4, 16]
    const float* b1 = (const float*)d_in[2];   // [17929, 4]
    const float* W2 = (const float*)d_in[3];   // [17929, 4]
    const float* b2 = (const float*)d_in[4];   // [17929]
    float* out = (float*)d_out;                // [512, 17929]

    cudaFuncSetAttribute(family_mlp_kernel,
                         cudaFuncAttributeMaxDynamicSharedMemorySize, SMEM_BYTES);

    dim3 grid((NUM_CLASSES + TILE_C - 1) / TILE_C, BATCH / RPC);   // 36 x 4 = 144 CTAs
    family_mlp_kernel<<<grid, TPB, SMEM_BYTES>>>(x, W1, b1, W2, b2, out);
}